// round 13
// baseline (speedup 1.0000x reference)
#include <cuda_runtime.h>
#include <cuda_fp16.h>
#include <cstdint>

// ---------------- problem constants ----------------
#define IN_CH  256
#define QB     36
#define BLK    64
#define KDIM   2304            // QB*BLK
#define NDIM   512
#define MDIM   8192

// ---------------- GEMM tiling ----------------
#define BM_   128
#define BN_   256
#define BKC   64               // K chunk (fp16) = 128 bytes
#define NIT   (KDIM / BKC)     // 36
#define NTHR  256              // 8 warps, 2x4 grid, 64x64 warp tile

#define STG_A 16384            // 128*64*2
#define STG_B 32768            // 256*64*2
#define STG   (STG_A + STG_B)  // 49152
#define NSTAGE 4
#define SMEM_TOTAL (NSTAGE * STG)      // 196608

// ---------------- scratch ----------------
__device__ __half g_Ah[(size_t)MDIM * KDIM];   // 37.7 MB
__device__ __half g_B [(size_t)NDIM * KDIM];   // 2.36 MB  [N][K] K-major

// ---------------- PTX helpers ----------------
__device__ __forceinline__ uint32_t smem_u32(const void* p) {
    uint32_t a;
    asm("{ .reg .u64 t; cvta.to.shared.u64 t, %1; cvt.u32.u64 %0, t; }"
        : "=r"(a) : "l"(p));
    return a;
}
__device__ __forceinline__ void cp16(uint32_t s, const void* g) {
    asm volatile("cp.async.cg.shared.global [%0], [%1], 16;" :: "r"(s), "l"(g));
}
#define CP_COMMIT() asm volatile("cp.async.commit_group;" ::: "memory")
#define CP_WAIT2()  asm volatile("cp.async.wait_group 2;" ::: "memory")

__device__ __forceinline__ void ldm4(uint32_t* r, uint32_t addr) {
    asm volatile("ldmatrix.sync.aligned.m8n8.x4.shared.b16 {%0,%1,%2,%3}, [%4];"
                 : "=r"(r[0]), "=r"(r[1]), "=r"(r[2]), "=r"(r[3]) : "r"(addr));
}
__device__ __forceinline__ void mma16816(float* c, const uint32_t* a, const uint32_t* b) {
    asm volatile(
        "mma.sync.aligned.m16n8k16.row.col.f32.f16.f16.f32 "
        "{%0,%1,%2,%3}, {%4,%5,%6,%7}, {%8,%9}, {%0,%1,%2,%3};"
        : "+f"(c[0]), "+f"(c[1]), "+f"(c[2]), "+f"(c[3])
        : "r"(a[0]), "r"(a[1]), "r"(a[2]), "r"(a[3]), "r"(b[0]), "r"(b[1]));
}

// ---------------------------------------------------------------------------
// Kernel 0: fused prep.  Blocks [0, 24576): im2col (4 elems/thread, 8B store).
//                        Blocks [24576, 26112): circulant weight expansion.
// ---------------------------------------------------------------------------
#define IM2COL_BLOCKS (3 * MDIM)                 // 24576, 192 thr, 4 elems
#define WPREP_BLOCKS  ((NDIM * KDIM) / (192*4))  // 1536
__global__ void prep_kernel(const float* __restrict__ x,
                            const float* __restrict__ w) {
    int bid = blockIdx.x;
    if (bid < IM2COL_BLOCKS) {
        int r  = bid / 3;
        int c0 = ((bid - r * 3) * 192 + threadIdx.x) * 4;  // 3*192*4 = 2304
        int b  = r >> 10;
        int rr = r & 1023;
        float v[4];
#pragma unroll
        for (int j = 0; j < 4; j++) {
            int g  = rr * KDIM + c0 + j;
            int f  = g >> 10;
            int l  = g & 1023;
            int cc = f / 9;
            int t  = f - cc * 9;
            int di = t / 3;
            int dj = t - di * 3;
            int ho = l >> 5;
            int wo = l & 31;
            int hi_ = ho + di - 1;
            int wi_ = wo + dj - 1;
            v[j] = 0.0f;
            if ((unsigned)hi_ < 32u && (unsigned)wi_ < 32u)
                v[j] = x[((b * IN_CH + cc) << 10) + (hi_ << 5) + wi_];
        }
        __half2 h01 = __floats2half2_rn(v[0], v[1]);
        __half2 h23 = __floats2half2_rn(v[2], v[3]);
        uint2 st;
        st.x = *(uint32_t*)&h01;
        st.y = *(uint32_t*)&h23;
        *(uint2*)(g_Ah + (size_t)r * KDIM + c0) = st;
    } else {
        // W[o][c] = w[p][q][(n-m)&63], o=p*64+n, c=q*64+m ; 4 c per thread
        int idx0 = ((bid - IM2COL_BLOCKS) * 192 + threadIdx.x) * 4;
        int o = idx0 / KDIM;
        int c = idx0 - o * KDIM;                 // KDIM%4==0 -> same row
        int p = o >> 6, n = o & 63;
        int q = c >> 6;                          // 4 consecutive c share q
        float v[4];
#pragma unroll
        for (int j = 0; j < 4; j++) {
            int m = (c + j) & 63;
            v[j] = w[(p * QB + q) * BLK + ((n - m) & 63)];
        }
        __half2 h01 = __floats2half2_rn(v[0], v[1]);
        __half2 h23 = __floats2half2_rn(v[2], v[3]);
        uint2 st;
        st.x = *(uint32_t*)&h01;
        st.y = *(uint32_t*)&h23;
        *(uint2*)(g_B + (size_t)o * KDIM + c) = st;
    }
}

// ---------------------------------------------------------------------------
// Kernel 1: fp16 mma.sync GEMM  C[8192,512] = Ah[8192,2304] * B[512,2304]^T
//   8 warps, 64x64 warp tile, register double-buffered fragments,
//   4-stage cp.async pipeline, one barrier per iteration.
// ---------------------------------------------------------------------------
extern __shared__ char dsm[];

__device__ __forceinline__ void load_stage(int it, int s, int tid,
                                           int rowTile, int colTile, uint32_t sb) {
    int kloc = it * BKC;
    const __half* Ab = g_Ah + (size_t)rowTile * KDIM + kloc;
    const __half* Bb = g_B  + (size_t)colTile * KDIM + kloc;
    uint32_t sA = sb + s * STG;
    uint32_t sB = sA + STG_A;
    // A: 128 rows x 8 chunks(16B) = 1024 -> 4 per thread
#pragma unroll
    for (int t = 0; t < 4; t++) {
        int i = tid + t * NTHR;
        int r = i >> 3, c = i & 7;
        cp16(sA + r * 128 + ((c ^ (r & 7)) << 4), Ab + (size_t)r * KDIM + c * 8);
    }
    // B: 256 rows x 8 chunks = 2048 -> 8 per thread
#pragma unroll
    for (int t = 0; t < 8; t++) {
        int i = tid + t * NTHR;
        int r = i >> 3, c = i & 7;
        cp16(sB + r * 128 + ((c ^ (r & 7)) << 4), Bb + (size_t)r * KDIM + c * 8);
    }
}

__global__ void __launch_bounds__(NTHR, 1) gemm_mma(float* __restrict__ out) {
    const int tid = threadIdx.x;
    const int wid = tid >> 5, lane = tid & 31;
    const int wm = wid >> 2, wn = wid & 3;          // 2x4 warp grid
    const int rowTile = blockIdx.y * BM_;
    const int colTile = blockIdx.x * BN_;
    const uint32_t sb = smem_u32(dsm);

    // ldmatrix lane-constant addressing
    const int quad = lane >> 3, rq = lane & 7;
    const int a_rowq = ((quad & 1) << 3) + rq;
    const int a_cq   = quad >> 1;
    const int a_xor  = a_rowq & 7;
    const int b_rowq = ((quad >> 1) << 3) + rq;
    const int b_cq   = quad & 1;
    const int b_xor  = b_rowq & 7;
    const uint32_t Aoff = (uint32_t)((wm * 64 + a_rowq) * 128);
    const uint32_t Boff = (uint32_t)(STG_A + (wn * 64 + b_rowq) * 128);

    float acc[4][8][4];
#pragma unroll
    for (int mt = 0; mt < 4; mt++)
#pragma unroll
        for (int j = 0; j < 8; j++)
#pragma unroll
            for (int v = 0; v < 4; v++) acc[mt][j][v] = 0.0f;

    load_stage(0, 0, tid, rowTile, colTile, sb);
    CP_COMMIT();
    load_stage(1, 1, tid, rowTile, colTile, sb);
    CP_COMMIT();
    load_stage(2, 2, tid, rowTile, colTile, sb);
    CP_COMMIT();

    uint32_t a[2][4][4], b[2][4][4];   // double-buffered fragments

#pragma unroll 1
    for (int it = 0; it < NIT; it++) {
        int s = it & 3;
        CP_WAIT2();            // <=2 groups outstanding -> chunk `it` resident
        __syncthreads();       // all warps done with iter it-1 (stage (it+3)%4 free)

        if (it + 3 < NIT)
            load_stage(it + 3, (it + 3) & 3, tid, rowTile, colTile, sb);
        CP_COMMIT();           // empty groups at tail keep bookkeeping valid

        uint32_t stageBase = sb + s * STG;
        uint32_t Ab = stageBase + Aoff;
        uint32_t Bb = stageBase + Boff;

        // preload k-slice 0 into buffer 0
#pragma unroll
        for (int mt = 0; mt < 4; mt++)
            ldm4(a[0][mt], Ab + mt * 2048 + (((0 + a_cq) ^ a_xor) << 4));
#pragma unroll
        for (int jp = 0; jp < 4; jp++)
            ldm4(b[0][jp], Bb + jp * 2048 + (((0 + b_cq) ^ b_xor) << 4));

#pragma unroll
        for (int ks = 0; ks < 4; ks++) {
            const int cur = ks & 1, nxt = cur ^ 1;
            if (ks < 3) {      // prefetch next k-slice while doing MMAs
#pragma unroll
                for (int mt = 0; mt < 4; mt++)
                    ldm4(a[nxt][mt],
                         Ab + mt * 2048 + ((((ks + 1) * 2 + a_cq) ^ a_xor) << 4));
#pragma unroll
                for (int jp = 0; jp < 4; jp++)
                    ldm4(b[nxt][jp],
                         Bb + jp * 2048 + ((((ks + 1) * 2 + b_cq) ^ b_xor) << 4));
            }
#pragma unroll
            for (int mt = 0; mt < 4; mt++)
#pragma unroll
                for (int j = 0; j < 8; j++)
                    mma16816(acc[mt][j], a[cur][mt], &b[cur][j >> 1][(j & 1) * 2]);
        }
    }

    // epilogue: C[r][o] -> out[b, o, rr]
    const int g = lane >> 2, tig = lane & 3;
    const int bb = rowTile >> 10;
    const int rrbase = (rowTile & 1023) + wm * 64;
#pragma unroll
    for (int mt = 0; mt < 4; mt++) {
#pragma unroll
        for (int j = 0; j < 8; j++) {
            int o = colTile + wn * 64 + j * 8 + tig * 2;
            int r0 = rrbase + mt * 16 + g;
            float* p0 = out + (((size_t)(bb * NDIM + o)) << 10);
            p0[r0]            = acc[mt][j][0];
            p0[1024 + r0]     = acc[mt][j][1];
            p0[r0 + 8]        = acc[mt][j][2];
            p0[1024 + r0 + 8] = acc[mt][j][3];
        }
    }
}

// ---------------------------------------------------------------------------
extern "C" void kernel_launch(void* const* d_in, const int* in_sizes, int n_in,
                              void* d_out, int out_size) {
    const float* x = (const float*)d_in[0];   // (8, 256, 32, 32) fp32
    const float* w = (const float*)d_in[1];   // (8, 36, 64) fp32
    float* out = (float*)d_out;               // (8, 512, 32, 32) fp32

    cudaFuncSetAttribute(gemm_mma, cudaFuncAttributeMaxDynamicSharedMemorySize,
                         SMEM_TOTAL);

    prep_kernel<<<IM2COL_BLOCKS + WPREP_BLOCKS, 192>>>(x, w);
    gemm_mma<<<dim3(NDIM / BN_, MDIM / BM_), NTHR, SMEM_TOTAL>>>(out);
}

// round 14
// speedup vs baseline: 1.0245x; 1.0245x over previous
#include <cuda_runtime.h>
#include <cuda_fp16.h>
#include <cstdint>

// ---------------- problem constants ----------------
#define IN_CH  256
#define QB     36
#define BLK    64
#define KDIM   2304            // QB*BLK
#define NDIM   512
#define MDIM   8192

// ---------------- GEMM tiling ----------------
#define BM_   128
#define BN_   256
#define BKC   128              // K chunk (fp16) = 2 sub-slabs of 64
#define NIT   (KDIM / BKC)     // 18
#define NTHR  256              // 8 warps, 2x4 grid, 64x64 warp tile

#define SUB_A 16384            // 128 rows * 128B (one 64-K sub-slab)
#define SUB_B 32768            // 256 rows * 128B
#define STG   (2*SUB_A + 2*SUB_B)      // 98304 : A0 A1 B0 B1
#define SMEM_TOTAL (2 * STG)           // 196608

// ---------------- scratch ----------------
__device__ __half g_Ah[(size_t)MDIM * KDIM];   // 37.7 MB
__device__ __half g_B [(size_t)NDIM * KDIM];   // 2.36 MB  [N][K] K-major

// ---------------- PTX helpers ----------------
__device__ __forceinline__ uint32_t smem_u32(const void* p) {
    uint32_t a;
    asm("{ .reg .u64 t; cvta.to.shared.u64 t, %1; cvt.u32.u64 %0, t; }"
        : "=r"(a) : "l"(p));
    return a;
}
__device__ __forceinline__ void cp16(uint32_t s, const void* g) {
    asm volatile("cp.async.cg.shared.global [%0], [%1], 16;" :: "r"(s), "l"(g));
}
#define CP_COMMIT() asm volatile("cp.async.commit_group;" ::: "memory")
#define CP_WAIT0()  asm volatile("cp.async.wait_group 0;" ::: "memory")

__device__ __forceinline__ void ldm4(uint32_t* r, uint32_t addr) {
    asm volatile("ldmatrix.sync.aligned.m8n8.x4.shared.b16 {%0,%1,%2,%3}, [%4];"
                 : "=r"(r[0]), "=r"(r[1]), "=r"(r[2]), "=r"(r[3]) : "r"(addr));
}
__device__ __forceinline__ void mma16816(float* c, const uint32_t* a, const uint32_t* b) {
    asm volatile(
        "mma.sync.aligned.m16n8k16.row.col.f32.f16.f16.f32 "
        "{%0,%1,%2,%3}, {%4,%5,%6,%7}, {%8,%9}, {%0,%1,%2,%3};"
        : "+f"(c[0]), "+f"(c[1]), "+f"(c[2]), "+f"(c[3])
        : "r"(a[0]), "r"(a[1]), "r"(a[2]), "r"(a[3]), "r"(b[0]), "r"(b[1]));
}

// ---------------------------------------------------------------------------
// Kernel 0: fused prep.  Blocks [0, 24576): im2col (4 elems/thread, 8B store).
//                        Blocks [24576, 26112): circulant weight expansion.
// ---------------------------------------------------------------------------
#define IM2COL_BLOCKS (3 * MDIM)                 // 24576, 192 thr, 4 elems
#define WPREP_BLOCKS  ((NDIM * KDIM) / (192*4))  // 1536
__global__ void prep_kernel(const float* __restrict__ x,
                            const float* __restrict__ w) {
    int bid = blockIdx.x;
    if (bid < IM2COL_BLOCKS) {
        int r  = bid / 3;
        int c0 = ((bid - r * 3) * 192 + threadIdx.x) * 4;  // 3*192*4 = 2304
        int b  = r >> 10;
        int rr = r & 1023;
        float v[4];
#pragma unroll
        for (int j = 0; j < 4; j++) {
            int g  = rr * KDIM + c0 + j;
            int f  = g >> 10;
            int l  = g & 1023;
            int cc = f / 9;
            int t  = f - cc * 9;
            int di = t / 3;
            int dj = t - di * 3;
            int ho = l >> 5;
            int wo = l & 31;
            int hi_ = ho + di - 1;
            int wi_ = wo + dj - 1;
            v[j] = 0.0f;
            if ((unsigned)hi_ < 32u && (unsigned)wi_ < 32u)
                v[j] = x[((b * IN_CH + cc) << 10) + (hi_ << 5) + wi_];
        }
        __half2 h01 = __floats2half2_rn(v[0], v[1]);
        __half2 h23 = __floats2half2_rn(v[2], v[3]);
        uint2 st;
        st.x = *(uint32_t*)&h01;
        st.y = *(uint32_t*)&h23;
        *(uint2*)(g_Ah + (size_t)r * KDIM + c0) = st;
    } else {
        // W[o][c] = w[p][q][(n-m)&63], o=p*64+n, c=q*64+m ; 4 c per thread
        int idx0 = ((bid - IM2COL_BLOCKS) * 192 + threadIdx.x) * 4;
        int o = idx0 / KDIM;
        int c = idx0 - o * KDIM;                 // KDIM%4==0 -> same row
        int p = o >> 6, n = o & 63;
        int q = c >> 6;                          // 4 consecutive c share q
        float v[4];
#pragma unroll
        for (int j = 0; j < 4; j++) {
            int m = (c + j) & 63;
            v[j] = w[(p * QB + q) * BLK + ((n - m) & 63)];
        }
        __half2 h01 = __floats2half2_rn(v[0], v[1]);
        __half2 h23 = __floats2half2_rn(v[2], v[3]);
        uint2 st;
        st.x = *(uint32_t*)&h01;
        st.y = *(uint32_t*)&h23;
        *(uint2*)(g_B + (size_t)o * KDIM + c) = st;
    }
}

// ---------------------------------------------------------------------------
// Kernel 1: fp16 mma.sync GEMM  C[8192,512] = Ah[8192,2304] * B[512,2304]^T
//   8 warps, 64x64 warp tile, register double-buffered fragments,
//   2-stage x 96KB pipeline (BKC=128), ONE barrier + ONE wait per iteration.
// ---------------------------------------------------------------------------
extern __shared__ char dsm[];

__device__ __forceinline__ void load_stage(int it, int s, int tid,
                                           int rowTile, int colTile, uint32_t sb) {
    int kloc = it * BKC;
    uint32_t st = sb + s * STG;
#pragma unroll
    for (int sub = 0; sub < 2; sub++) {
        const __half* Ab = g_Ah + (size_t)rowTile * KDIM + kloc + sub * 64;
        const __half* Bb = g_B  + (size_t)colTile * KDIM + kloc + sub * 64;
        uint32_t sA = st + sub * SUB_A;
        uint32_t sB = st + 2 * SUB_A + sub * SUB_B;
        // A sub-slab: 128 rows x 8 chunks(16B) = 1024 -> 4 per thread
#pragma unroll
        for (int t = 0; t < 4; t++) {
            int i = tid + t * NTHR;
            int r = i >> 3, c = i & 7;
            cp16(sA + r * 128 + ((c ^ (r & 7)) << 4), Ab + (size_t)r * KDIM + c * 8);
        }
        // B sub-slab: 256 rows x 8 chunks = 2048 -> 8 per thread
#pragma unroll
        for (int t = 0; t < 8; t++) {
            int i = tid + t * NTHR;
            int r = i >> 3, c = i & 7;
            cp16(sB + r * 128 + ((c ^ (r & 7)) << 4), Bb + (size_t)r * KDIM + c * 8);
        }
    }
}

__global__ void __launch_bounds__(NTHR, 1) gemm_mma(float* __restrict__ out) {
    const int tid = threadIdx.x;
    const int wid = tid >> 5, lane = tid & 31;
    const int wm = wid >> 2, wn = wid & 3;          // 2x4 warp grid
    const int rowTile = blockIdx.y * BM_;
    const int colTile = blockIdx.x * BN_;
    const uint32_t sb = smem_u32(dsm);

    // ldmatrix lane-constant addressing
    const int quad = lane >> 3, rq = lane & 7;
    const int a_rowq = ((quad & 1) << 3) + rq;
    const int a_cq   = quad >> 1;
    const int a_xor  = a_rowq & 7;
    const int b_rowq = ((quad >> 1) << 3) + rq;
    const int b_cq   = quad & 1;
    const int b_xor  = b_rowq & 7;
    const uint32_t Aoff = (uint32_t)((wm * 64 + a_rowq) * 128);
    const uint32_t Boff = (uint32_t)(2 * SUB_A + (wn * 64 + b_rowq) * 128);

    float acc[4][8][4];
#pragma unroll
    for (int mt = 0; mt < 4; mt++)
#pragma unroll
        for (int j = 0; j < 8; j++)
#pragma unroll
            for (int v = 0; v < 4; v++) acc[mt][j][v] = 0.0f;

    load_stage(0, 0, tid, rowTile, colTile, sb);
    CP_COMMIT();

    uint32_t a[2][4][4], b[2][4][4];   // double-buffered fragments

#pragma unroll 1
    for (int it = 0; it < NIT; it++) {
        int s = it & 1;
        CP_WAIT0();            // all outstanding groups (i.e. chunk `it`) resident
        __syncthreads();       // chip-visible + stage s^1 fully drained by all warps

        if (it + 1 < NIT) {    // overlap window = this whole iteration's compute
            load_stage(it + 1, s ^ 1, tid, rowTile, colTile, sb);
            CP_COMMIT();
        }

        uint32_t stageBase = sb + s * STG;
        uint32_t Ab = stageBase + Aoff;
        uint32_t Bb = stageBase + Boff;

        // preload k-slice 0 (sub 0, ks 0) into buffer 0
#pragma unroll
        for (int mt = 0; mt < 4; mt++)
            ldm4(a[0][mt], Ab + mt * 2048 + ((a_cq ^ a_xor) << 4));
#pragma unroll
        for (int jp = 0; jp < 4; jp++)
            ldm4(b[0][jp], Bb + jp * 2048 + ((b_cq ^ b_xor) << 4));

#pragma unroll
        for (int kk = 0; kk < 8; kk++) {
            const int cur = kk & 1, nxt = cur ^ 1;
            if (kk < 7) {      // prefetch next k-slice while doing MMAs
                const int ksn = (kk + 1) & 3, subn = (kk + 1) >> 2;
                uint32_t An = Ab + subn * SUB_A;
                uint32_t Bn = Bb + subn * SUB_B;
#pragma unroll
                for (int mt = 0; mt < 4; mt++)
                    ldm4(a[nxt][mt],
                         An + mt * 2048 + (((ksn * 2 + a_cq) ^ a_xor) << 4));
#pragma unroll
                for (int jp = 0; jp < 4; jp++)
                    ldm4(b[nxt][jp],
                         Bn + jp * 2048 + (((ksn * 2 + b_cq) ^ b_xor) << 4));
            }
#pragma unroll
            for (int mt = 0; mt < 4; mt++)
#pragma unroll
                for (int j = 0; j < 8; j++)
                    mma16816(acc[mt][j], a[cur][mt], &b[cur][j >> 1][(j & 1) * 2]);
        }
    }

    // epilogue: C[r][o] -> out[b, o, rr]
    const int g = lane >> 2, tig = lane & 3;
    const int bb = rowTile >> 10;
    const int rrbase = (rowTile & 1023) + wm * 64;
#pragma unroll
    for (int mt = 0; mt < 4; mt++) {
#pragma unroll
        for (int j = 0; j < 8; j++) {
            int o = colTile + wn * 64 + j * 8 + tig * 2;
            int r0 = rrbase + mt * 16 + g;
            float* p0 = out + (((size_t)(bb * NDIM + o)) << 10);
            p0[r0]            = acc[mt][j][0];
            p0[1024 + r0]     = acc[mt][j][1];
            p0[r0 + 8]        = acc[mt][j][2];
            p0[1024 + r0 + 8] = acc[mt][j][3];
        }
    }
}

// ---------------------------------------------------------------------------
extern "C" void kernel_launch(void* const* d_in, const int* in_sizes, int n_in,
                              void* d_out, int out_size) {
    const float* x = (const float*)d_in[0];   // (8, 256, 32, 32) fp32
    const float* w = (const float*)d_in[1];   // (8, 36, 64) fp32
    float* out = (float*)d_out;               // (8, 512, 32, 32) fp32

    cudaFuncSetAttribute(gemm_mma, cudaFuncAttributeMaxDynamicSharedMemorySize,
                         SMEM_TOTAL);

    prep_kernel<<<IM2COL_BLOCKS + WPREP_BLOCKS, 192>>>(x, w);
    gemm_mma<<<dim3(NDIM / BN_, MDIM / BM_), NTHR, SMEM_TOTAL>>>(out);
}